// round 5
// baseline (speedup 1.0000x reference)
#include <cuda_runtime.h>
#include <cuda_bf16.h>
#include <cstdint>
#include <cstddef>

#define BATCH   4
#define CIN     64
#define COUT    128
#define HH      64
#define WW      1024
#define HO      32
#define WO      512
#define NPIX    65536
#define KTOT    1024
#define OUT0    8388608
#define AZI_C   0.006135923151542565f
#define INC_C   0.0073f

// scratch: m split into bf16 hi/lo planes, [k][n] layout, n contiguous
__device__ __nv_bfloat16 g_mh[(size_t)KTOT * NPIX];
__device__ __nv_bfloat16 g_ml[(size_t)KTOT * NPIX];
__device__ __nv_bfloat16 g_WcH[COUT * KTOT];
__device__ __nv_bfloat16 g_WcL[COUT * KTOT];
__device__ __nv_bfloat16 g_W2TH[CIN * CIN];   // [c][j]
__device__ __nv_bfloat16 g_W2TL[CIN * CIN];

__device__ __forceinline__ uint32_t smem_u32(const void* p) {
    uint32_t a;
    asm("{ .reg .u64 t; cvta.to.shared.u64 t, %1; cvt.u32.u64 %0, t; }" : "=r"(a) : "l"(p));
    return a;
}
// swizzles for 128B / 256B / 512B row strides (Swizzle<3,4,3> family)
#define SWA(o) ((o) ^ (((o) >> 3) & 0x70))
#define SWB(o) ((o) ^ (((o) >> 4) & 0x70))
#define SWC(o) ((o) ^ (((o) >> 5) & 0x70))

__device__ __forceinline__ void cp16(uint32_t saddr, const void* gaddr) {
    asm volatile("cp.async.cg.shared.global [%0], [%1], 16;" :: "r"(saddr), "l"(gaddr));
}
#define CP_COMMIT() asm volatile("cp.async.commit_group;" ::: "memory")
#define CP_WAIT1()  asm volatile("cp.async.wait_group 1;" ::: "memory")
#define CP_WAIT0()  asm volatile("cp.async.wait_group 0;" ::: "memory")

__device__ __forceinline__ void ldsm4(uint32_t* r, uint32_t a) {
    asm volatile("ldmatrix.sync.aligned.m8n8.x4.shared.b16 {%0,%1,%2,%3}, [%4];"
        : "=r"(r[0]), "=r"(r[1]), "=r"(r[2]), "=r"(r[3]) : "r"(a));
}
__device__ __forceinline__ void ldsm4t(uint32_t* r, uint32_t a) {
    asm volatile("ldmatrix.sync.aligned.m8n8.x4.trans.shared.b16 {%0,%1,%2,%3}, [%4];"
        : "=r"(r[0]), "=r"(r[1]), "=r"(r[2]), "=r"(r[3]) : "r"(a));
}
__device__ __forceinline__ void mma16816(float* d, const uint32_t* a, const uint32_t* b) {
    asm volatile(
        "mma.sync.aligned.m16n8k16.row.col.f32.bf16.bf16.f32 "
        "{%0,%1,%2,%3}, {%4,%5,%6,%7}, {%8,%9}, {%0,%1,%2,%3};"
        : "+f"(d[0]), "+f"(d[1]), "+f"(d[2]), "+f"(d[3])
        : "r"(a[0]), "r"(a[1]), "r"(a[2]), "r"(a[3]), "r"(b[0]), "r"(b[1]));
}

// =====================================================================
// Kernel 0: split Wc -> bf16 hi/lo ([o][k]) and W2^T -> bf16 hi/lo ([c][j])
// =====================================================================
__global__ void k0_prep(const float* __restrict__ Wc, const float* __restrict__ W2) {
    int i = blockIdx.x * 256 + threadIdx.x;
    if (i < COUT * KTOT) {
        float v = Wc[i];
        __nv_bfloat16 h = __float2bfloat16(v);
        g_WcH[i] = h;
        g_WcL[i] = __float2bfloat16(v - __bfloat162float(h));
    }
    if (i < CIN * CIN) {
        int j = i >> 6, c = i & 63;
        float v = W2[i];
        __nv_bfloat16 h = __float2bfloat16(v);
        g_W2TH[c * 64 + j] = h;
        g_W2TL[c * 64 + j] = __float2bfloat16(v - __bfloat162float(h));
    }
}

// =====================================================================
// Kernel 1: h(bf16 split) -> HMMA w-GEMM -> m = w*x (x from smem) -> g_m
// grid (16, 32, 4), 256 threads, 1 CTA/SM.
// smem bytes:
//   ws   f32 [64][260]             0      66560
//   xs   f32 [64][4][66]           66560  67584
//   hsH  bf16 [64][256] 512B rows  134144 32768
//   hsL                             166912 32768
//   W2TH bf16 [64][64] 128B rows   199680 8192
//   W2TL                            207872 8192
//   Ast  f32 [64][16]              216064 4096
//   W10s/b1s/b2s f32 64 each       220160 768
//   rs   f32 [4][66]               220928 1056  -> total 221984
// =====================================================================
#define WS_F    0
#define XS_F    16640
#define HSH_B   134144
#define HSL_B   166912
#define W2TH_B  199680
#define W2TL_B  207872
#define AST_F   54016
#define W10_F   55040
#define B1_F    55104
#define B2_F    55168
#define RS_F    55232
#define SM1_BYTES 221984

__global__ void __launch_bounds__(256, 1)
k1_weights(const float* __restrict__ x, const float* __restrict__ r,
           const float* __restrict__ W1, const float* __restrict__ b1,
           const float* __restrict__ b2, float* __restrict__ rcout)
{
    extern __shared__ float sm[];
    float* ws   = sm + WS_F;     // [64][260]
    float* xs   = sm + XS_F;     // [64][264] = [64][4][66]
    float* Ast  = sm + AST_F;
    float* W10s = sm + W10_F;
    float* b1s  = sm + B1_F;
    float* b2s  = sm + B2_F;
    float* rs   = sm + RS_F;
    char*  smc  = (char*)sm;
    const uint32_t sb = smem_u32(sm);

    const int tid  = threadIdx.x;
    const int lane = tid & 31;
    const int wid  = tid >> 5;
    const int ho   = blockIdx.y;
    const int bz   = blockIdx.z;
    const int wo0  = blockIdx.x * 32;

    // ---- stage constants ----
    if (tid < 64) { W10s[tid] = W1[tid]; b1s[tid] = b1[tid]; b2s[tid] = b2[tid]; }
    for (int i = tid; i < 1024; i += 256) {
        int j = i >> 4, pos = i & 15;
        int u = pos >> 2, v = pos & 3;
        float du = (float)(u - 2), dv = (float)(v - 2);
        float ca = cosf(AZI_C * dv), sa = sinf(AZI_C * dv);
        float ci = cosf(INC_C * du), si = sinf(INC_C * du);
        Ast[i] = ca * ci * W1[j] + ca * si * W1[64 + j] + sa * W1[128 + j];
    }
    for (int i = tid; i < 4 * 66; i += 256) {
        int v = i / 66, cc = i % 66;
        int rowp = 2 * ho + v;
        int row  = (rowp == 0) ? (HH - 1) : ((rowp == HH + 1) ? 0 : rowp - 1);
        int colp = 2 * wo0 + cc;
        float val;
        if (colp == 0 || colp == WW + 1) val = 100.0f;
        else val = r[((size_t)bz * HH + row) * WW + (colp - 1)];
        rs[i] = val;
    }
    // W2T planes into swizzled smem
    for (int i = tid; i < 4096; i += 256) {
        int row = i >> 6, col = i & 63;
        uint32_t off = SWA(row * 128 + col * 2);
        *(__nv_bfloat16*)(smc + W2TH_B + off) = g_W2TH[i];
        *(__nv_bfloat16*)(smc + W2TL_B + off) = g_W2TL[i];
    }
    // x strip: xs[c][v][0..65], global col = 2*wo0 - 1 + cc (pad 0 at -1/1024)
    {
        int xr[4];
        #pragma unroll
        for (int v = 0; v < 4; v++) {
            int rowp = 2 * ho + v;
            xr[v] = (rowp == 0) ? (HH - 1) : ((rowp == HH + 1) ? 0 : rowp - 1);
        }
        for (int i = tid; i < 64 * 4 * 66; i += 256) {
            int rr = i / 66, cc = i % 66;
            int c = rr >> 2, v = rr & 3;
            int g = 2 * wo0 - 1 + cc;
            float val = 0.0f;
            if (g >= 0 && g < WW)
                val = x[(((size_t)(bz * CIN + c)) * HH + xr[v]) * WW + g];
            xs[c * 264 + v * 66 + cc] = val;
        }
    }
    __syncthreads();

    const size_t nbase = (size_t)bz * 16384 + (size_t)ho * 512 + wo0;
    const int wm = (wid & 1) * 32;      // GEMM warp M (c) offset
    const int wn = (wid >> 1) * 64;     // GEMM warp N (combo) offset

    for (int s = 0; s < 2; s++) {
        // ---- h compute + bf16 hi/lo split -> hs (SWC swizzled, 512B rows) ----
        {
            int posl = tid >> 5;
            int pos  = 8 * s + posl;
            int u = pos >> 2, v = pos & 3;
            int px = tid & 31;
            float R   = rs[v * 66 + 2 * px + u];
            float nrc = -rs[2 * 66 + 2 * px + 2];
            #pragma unroll 8
            for (int j = 0; j < 64; j++) {
                float t = fmaf(R, Ast[j * 16 + pos], fmaf(nrc, W10s[j], b1s[j]));
                t = (t > 0.0f) ? t : 0.2f * t;
                __nv_bfloat16 hi = __float2bfloat16(t);
                float rem = t - __bfloat162float(hi);
                uint32_t off = SWC(j * 512 + tid * 2);
                *(__nv_bfloat16*)(smc + HSH_B + off) = hi;
                *(__nv_bfloat16*)(smc + HSL_B + off) = __float2bfloat16(rem);
            }
        }
        __syncthreads();

        // ---- HMMA GEMM: w[c][combo] = b2[c] + sum_j W2T[c][j]*h[j][combo] ----
        {
            float acc[2][8][4];
            #pragma unroll
            for (int mi = 0; mi < 2; mi++)
                #pragma unroll
                for (int nt = 0; nt < 8; nt++)
                    #pragma unroll
                    for (int q = 0; q < 4; q++) acc[mi][nt][q] = 0.0f;

            #pragma unroll
            for (int ks = 0; ks < 4; ks++) {
                uint32_t aH[2][4], aL[2][4];
                int arow  = wm + (lane & 15);
                int acolb = ks * 32 + ((lane >> 4) << 4);
                #pragma unroll
                for (int mi = 0; mi < 2; mi++) {
                    uint32_t off = SWA((arow + mi * 16) * 128 + acolb);
                    ldsm4(aH[mi], sb + W2TH_B + off);
                    ldsm4(aL[mi], sb + W2TL_B + off);
                }
                int browb = (ks * 16 + (lane & 15)) * 512;
                #pragma unroll
                for (int g = 0; g < 4; g++) {
                    uint32_t off = SWC(browb + wn * 2 + g * 32 + ((lane >> 4) << 4));
                    uint32_t bh[4], bl[4];
                    ldsm4t(bh, sb + HSH_B + off);
                    ldsm4t(bl, sb + HSL_B + off);
                    #pragma unroll
                    for (int mi = 0; mi < 2; mi++) {
                        mma16816(acc[mi][2*g],   aH[mi], bh);
                        mma16816(acc[mi][2*g+1], aH[mi], bh + 2);
                        mma16816(acc[mi][2*g],   aL[mi], bh);
                        mma16816(acc[mi][2*g+1], aL[mi], bh + 2);
                        mma16816(acc[mi][2*g],   aH[mi], bl);
                        mma16816(acc[mi][2*g+1], aH[mi], bl + 2);
                    }
                }
            }

            // acc -> ws with bias
            #pragma unroll
            for (int mi = 0; mi < 2; mi++) {
                int r0 = wm + mi * 16 + (lane >> 2);
                float b2a = b2s[r0], b2b = b2s[r0 + 8];
                #pragma unroll
                for (int nt = 0; nt < 8; nt++) {
                    int col = wn + nt * 8 + (lane & 3) * 2;
                    float2 v0, v1;
                    v0.x = acc[mi][nt][0] + b2a; v0.y = acc[mi][nt][1] + b2a;
                    v1.x = acc[mi][nt][2] + b2b; v1.y = acc[mi][nt][3] + b2b;
                    *(float2*)(ws + r0 * 260 + col) = v0;
                    *(float2*)(ws + (r0 + 8) * 260 + col) = v1;
                }
            }
        }
        __syncthreads();

        // ---- phase B: m = w * x -> bf16 hi/lo to g_m ----
        {
            int posl = wid;
            int pos  = 8 * s + posl;
            int u = pos >> 2, v = pos & 3;
            int px = lane;
            const float* xrow = xs + v * 66 + 2 * px + u;
            const float* wsr  = ws + posl * 32 + px;
            __nv_bfloat16* gmh = g_mh + (size_t)pos * NPIX + nbase + px;
            __nv_bfloat16* gml = g_ml + (size_t)pos * NPIX + nbase + px;
            #pragma unroll 8
            for (int c = 0; c < 64; c++) {
                float wv = wsr[c * 260];
                float xv = xrow[c * 264];
                float mv = wv * xv;
                __nv_bfloat16 hi = __float2bfloat16(mv);
                float rem = mv - __bfloat162float(hi);
                gmh[(size_t)c * 16 * NPIX] = hi;
                gml[(size_t)c * 16 * NPIX] = __float2bfloat16(rem);
            }
        }
        __syncthreads();
    }

    if (rcout != nullptr && tid < 32) {
        rcout[nbase + tid] = rs[2 * 66 + 2 * tid + 2];
    }
}

// =====================================================================
// Kernel 2: HMMA bf16 split GEMM (unchanged from R4).
// =====================================================================
#define K2_STAGE 65536
#define K2_SMEM  (2 * K2_STAGE)

__global__ void __launch_bounds__(256, 1)
k2_hmma(const float* __restrict__ bc, float* __restrict__ out)
{
    extern __shared__ char sm2[];
    const uint32_t sb = smem_u32(sm2);
    const int tid  = threadIdx.x;
    const int wid  = tid >> 5;
    const int lane = tid & 31;
    const int n0 = blockIdx.x * 128;
    const int wm = (wid & 3) * 32;
    const int wn = (wid >> 2) * 64;

    float acc[2][8][4];
    #pragma unroll
    for (int mi = 0; mi < 2; mi++)
        #pragma unroll
        for (int nt = 0; nt < 8; nt++)
            #pragma unroll
            for (int q = 0; q < 4; q++) acc[mi][nt][q] = 0.0f;

    auto load_chunk = [&](int c, int s) {
        const uint32_t base = sb + s * K2_STAGE;
        const int k0 = c * 64;
        #pragma unroll
        for (int t = 0; t < 16; t++) {
            int ci  = tid + t * 256;
            int sec = t >> 2;
            int ci0 = ci & 1023;
            if (sec < 2) {
                const __nv_bfloat16* W = sec ? g_WcL : g_WcH;
                int row = ci0 >> 3, u = ci0 & 7;
                uint32_t sa = base + sec * 16384 + SWA(row * 128 + u * 16);
                cp16(sa, W + (size_t)row * KTOT + k0 + u * 8);
            } else {
                const __nv_bfloat16* M = (sec == 2) ? g_mh : g_ml;
                int row = ci0 >> 4, u = ci0 & 15;
                uint32_t sa = base + sec * 16384 + SWB(row * 256 + u * 16);
                cp16(sa, M + (size_t)(k0 + row) * NPIX + n0 + u * 8);
            }
        }
        CP_COMMIT();
    };

    load_chunk(0, 0);
    load_chunk(1, 1);

    for (int c = 0; c < 16; c++) {
        const int s = c & 1;
        if (c == 15) { CP_WAIT0(); } else { CP_WAIT1(); }
        __syncthreads();

        const uint32_t bAh = sb + s * K2_STAGE;
        const uint32_t bAl = bAh + 16384;
        const uint32_t bBh = bAh + 32768;
        const uint32_t bBl = bAh + 49152;

        #pragma unroll
        for (int ks = 0; ks < 4; ks++) {
            uint32_t a_h[2][4], a_l[2][4];
            {
                int arow  = wm + (lane & 15);
                int acolb = ks * 32 + ((lane >> 4) << 4);
                #pragma unroll
                for (int mi = 0; mi < 2; mi++) {
                    uint32_t off = SWA((arow + mi * 16) * 128 + acolb);
                    ldsm4(a_h[mi], bAh + off);
                    ldsm4(a_l[mi], bAl + off);
                }
            }
            int brow = ks * 16 + (lane & 15);
            #pragma unroll
            for (int g = 0; g < 4; g++) {
                int bcolb = (wn + g * 16 + ((lane >> 4) << 3)) * 2;
                uint32_t off = SWB(brow * 256 + bcolb);
                uint32_t bh[4], bl[4];
                ldsm4t(bh, bBh + off);
                ldsm4t(bl, bBl + off);
                #pragma unroll
                for (int mi = 0; mi < 2; mi++) {
                    mma16816(acc[mi][2*g],   a_h[mi], bh);
                    mma16816(acc[mi][2*g+1], a_h[mi], bh + 2);
                    mma16816(acc[mi][2*g],   a_l[mi], bh);
                    mma16816(acc[mi][2*g+1], a_l[mi], bh + 2);
                    mma16816(acc[mi][2*g],   a_h[mi], bl);
                    mma16816(acc[mi][2*g+1], a_h[mi], bl + 2);
                }
            }
        }
        __syncthreads();
        if (c + 2 < 16) load_chunk(c + 2, s);
    }

    const int bz = n0 >> 14;
    #pragma unroll
    for (int mi = 0; mi < 2; mi++) {
        int r0 = wm + mi * 16 + (lane >> 2);
        float bv0 = bc[r0], bv1 = bc[r0 + 8];
        float* row0 = out + ((size_t)(bz * COUT + r0))     * 16384 + (n0 & 16383);
        float* row1 = out + ((size_t)(bz * COUT + r0 + 8)) * 16384 + (n0 & 16383);
        #pragma unroll
        for (int nt = 0; nt < 8; nt++) {
            int col = wn + nt * 8 + (lane & 3) * 2;
            float2 v0, v1;
            v0.x = acc[mi][nt][0] + bv0; v0.y = acc[mi][nt][1] + bv0;
            v1.x = acc[mi][nt][2] + bv1; v1.y = acc[mi][nt][3] + bv1;
            *(float2*)(row0 + col) = v0;
            *(float2*)(row1 + col) = v1;
        }
    }
}

extern "C" void kernel_launch(void* const* d_in, const int* in_sizes, int n_in,
                              void* d_out, int out_size) {
    const float* x  = (const float*)d_in[0];
    const float* r  = (const float*)d_in[1];
    const float* W1 = (const float*)d_in[2];
    const float* b1 = (const float*)d_in[3];
    const float* W2 = (const float*)d_in[4];
    const float* b2 = (const float*)d_in[5];
    const float* Wc = (const float*)d_in[6];
    const float* bc = (const float*)d_in[7];
    float* out = (float*)d_out;

    cudaFuncSetAttribute(k1_weights, cudaFuncAttributeMaxDynamicSharedMemorySize, SM1_BYTES);
    cudaFuncSetAttribute(k2_hmma, cudaFuncAttributeMaxDynamicSharedMemorySize, K2_SMEM);

    float* rcout = (out_size > OUT0) ? (out + OUT0) : nullptr;

    k0_prep<<<(COUT * KTOT + 255) / 256, 256>>>(Wc, W2);
    dim3 g1(16, 32, 4);
    k1_weights<<<g1, 256, SM1_BYTES>>>(x, r, W1, b1, b2, rcout);
    k2_hmma<<<512, 256, K2_SMEM>>>(bc, out);
}

// round 7
// speedup vs baseline: 1.3506x; 1.3506x over previous
#include <cuda_runtime.h>
#include <cuda_bf16.h>
#include <cstdint>
#include <cstddef>

#define BATCH   4
#define CIN     64
#define COUT    128
#define HH      64
#define WW      1024
#define HO      32
#define WO      512
#define NPIX    65536
#define KTOT    1024
#define OUT0    8388608
#define AZI_C   0.006135923151542565f
#define INC_C   0.0073f

__device__ __nv_bfloat16 g_mh[(size_t)KTOT * NPIX];
__device__ __nv_bfloat16 g_ml[(size_t)KTOT * NPIX];
__device__ __nv_bfloat16 g_WcH[COUT * KTOT];
__device__ __nv_bfloat16 g_WcL[COUT * KTOT];
__device__ __nv_bfloat16 g_W2TH[CIN * CIN];   // [c][j]
__device__ __nv_bfloat16 g_W2TL[CIN * CIN];
__device__ float g_Ast[CIN * 16];             // [j][pos]

__device__ __forceinline__ uint32_t smem_u32(const void* p) {
    uint32_t a;
    asm("{ .reg .u64 t; cvta.to.shared.u64 t, %1; cvt.u32.u64 %0, t; }" : "=r"(a) : "l"(p));
    return a;
}
#define SWA(o) ((o) ^ (((o) >> 3) & 0x70))
#define SWB(o) ((o) ^ (((o) >> 4) & 0x70))
#define SWC(o) ((o) ^ (((o) >> 5) & 0x70))

__device__ __forceinline__ void sts32(uint32_t saddr, uint32_t v) {
    asm volatile("st.shared.u32 [%0], %1;" :: "r"(saddr), "r"(v) : "memory");
}
__device__ __forceinline__ void cp16(uint32_t saddr, const void* gaddr) {
    asm volatile("cp.async.cg.shared.global [%0], [%1], 16;" :: "r"(saddr), "l"(gaddr));
}
#define CP_COMMIT() asm volatile("cp.async.commit_group;" ::: "memory")
#define CP_WAIT1()  asm volatile("cp.async.wait_group 1;" ::: "memory")
#define CP_WAIT0()  asm volatile("cp.async.wait_group 0;" ::: "memory")

__device__ __forceinline__ void ldsm4(uint32_t* r, uint32_t a) {
    asm volatile("ldmatrix.sync.aligned.m8n8.x4.shared.b16 {%0,%1,%2,%3}, [%4];"
        : "=r"(r[0]), "=r"(r[1]), "=r"(r[2]), "=r"(r[3]) : "r"(a));
}
__device__ __forceinline__ void ldsm4t(uint32_t* r, uint32_t a) {
    asm volatile("ldmatrix.sync.aligned.m8n8.x4.trans.shared.b16 {%0,%1,%2,%3}, [%4];"
        : "=r"(r[0]), "=r"(r[1]), "=r"(r[2]), "=r"(r[3]) : "r"(a));
}
__device__ __forceinline__ void mma16816(float* d, const uint32_t* a, const uint32_t* b) {
    asm volatile(
        "mma.sync.aligned.m16n8k16.row.col.f32.bf16.bf16.f32 "
        "{%0,%1,%2,%3}, {%4,%5,%6,%7}, {%8,%9}, {%0,%1,%2,%3};"
        : "+f"(d[0]), "+f"(d[1]), "+f"(d[2]), "+f"(d[3])
        : "r"(a[0]), "r"(a[1]), "r"(a[2]), "r"(a[3]), "r"(b[0]), "r"(b[1]));
}
// pack: lo -> lower 16 bits, hi -> upper 16 bits
__device__ __forceinline__ uint32_t pk_bf2(float lo, float hi) {
    uint32_t r;
    asm("cvt.rn.bf16x2.f32 %0, %1, %2;" : "=r"(r) : "f"(hi), "f"(lo));
    return r;
}

// =====================================================================
// Kernel 0: split Wc + W2^T into bf16 hi/lo, precompute Ast
// =====================================================================
__global__ void k0_prep(const float* __restrict__ Wc, const float* __restrict__ W2,
                        const float* __restrict__ W1) {
    int i = blockIdx.x * 256 + threadIdx.x;
    if (i < COUT * KTOT) {
        float v = Wc[i];
        __nv_bfloat16 h = __float2bfloat16(v);
        g_WcH[i] = h;
        g_WcL[i] = __float2bfloat16(v - __bfloat162float(h));
    }
    if (i < CIN * CIN) {
        int j = i >> 6, c = i & 63;
        float v = W2[i];
        __nv_bfloat16 h = __float2bfloat16(v);
        g_W2TH[c * 64 + j] = h;
        g_W2TL[c * 64 + j] = __float2bfloat16(v - __bfloat162float(h));
    }
    if (i < CIN * 16) {
        int j = i >> 4, pos = i & 15;
        int u = pos >> 2, v = pos & 3;
        float du = (float)(u - 2), dv = (float)(v - 2);
        float ca = cosf(AZI_C * dv), sa = sinf(AZI_C * dv);
        float ci = cosf(INC_C * du), si = sinf(INC_C * du);
        g_Ast[i] = ca * ci * W1[j] + ca * si * W1[64 + j] + sa * W1[128 + j];
    }
}

// =====================================================================
// Kernel 1: h (shfl-packed bf16x2 split) -> HMMA w-GEMM -> m = w*x -> g_m
// grid (16, 32, 4), 256 threads, 1 CTA/SM.
// =====================================================================
#define WS_F    0
#define XS_F    16640
#define HSH_B   134144
#define HSL_B   166912
#define W2TH_B  199680
#define W2TL_B  207872
#define AST_F   54016
#define W10_F   55040
#define B1_F    55104
#define B2_F    55168
#define RS_F    55232
#define SM1_BYTES 221984

__global__ void __launch_bounds__(256, 1)
k1_weights(const float* __restrict__ x, const float* __restrict__ r,
           const float* __restrict__ W1, const float* __restrict__ b1,
           const float* __restrict__ b2, float* __restrict__ rcout)
{
    extern __shared__ float sm[];
    float* ws   = sm + WS_F;     // f32 [64][260]
    float* xs   = sm + XS_F;     // f32 [64][264] = [64][4][66]
    float* Ast  = sm + AST_F;
    float* W10s = sm + W10_F;
    float* b1s  = sm + B1_F;
    float* b2s  = sm + B2_F;
    float* rs   = sm + RS_F;
    char*  smc  = (char*)sm;
    const uint32_t sb = smem_u32(sm);

    const int tid  = threadIdx.x;
    const int lane = tid & 31;
    const int wid  = tid >> 5;
    const int ho   = blockIdx.y;
    const int bz   = blockIdx.z;
    const int wo0  = blockIdx.x * 32;

    if (tid < 64) { W10s[tid] = W1[tid]; b1s[tid] = b1[tid]; b2s[tid] = b2[tid]; }
    for (int i = tid; i < 1024; i += 256) Ast[i] = g_Ast[i];
    for (int i = tid; i < 4 * 66; i += 256) {
        int v = i / 66, cc = i % 66;
        int rowp = 2 * ho + v;
        int row  = (rowp == 0) ? (HH - 1) : ((rowp == HH + 1) ? 0 : rowp - 1);
        int colp = 2 * wo0 + cc;
        float val;
        if (colp == 0 || colp == WW + 1) val = 100.0f;
        else val = r[((size_t)bz * HH + row) * WW + (colp - 1)];
        rs[i] = val;
    }
    for (int i = tid; i < 4096; i += 256) {
        int row = i >> 6, col = i & 63;
        uint32_t off = SWA(row * 128 + col * 2);
        *(__nv_bfloat16*)(smc + W2TH_B + off) = g_W2TH[i];
        *(__nv_bfloat16*)(smc + W2TL_B + off) = g_W2TL[i];
    }
    // x strip, division-free
    {
        int xr[4];
        #pragma unroll
        for (int v = 0; v < 4; v++) {
            int rowp = 2 * ho + v;
            xr[v] = (rowp == 0) ? (HH - 1) : ((rowp == HH + 1) ? 0 : rowp - 1);
        }
        const int gbase = 2 * wo0 - 1;
        #pragma unroll 4
        for (int it = 0; it < 64; it++) {
            int flat = tid + it * 256;
            int cc = flat & 63;
            int rv = flat >> 6;
            int c = rv >> 2, v = rv & 3;
            int g = gbase + cc;
            float val = 0.0f;
            if (g >= 0)
                val = x[(((size_t)(bz * CIN + c)) * HH + xr[v]) * WW + g];
            xs[c * 264 + v * 66 + cc] = val;
        }
        for (int it = 0; it < 2; it++) {
            int flat = tid + it * 256;
            int cc = 64 + (flat & 1);
            int rv = flat >> 1;
            int c = rv >> 2, v = rv & 3;
            int g = gbase + cc;
            float val = 0.0f;
            if (g < WW)
                val = x[(((size_t)(bz * CIN + c)) * HH + xr[v]) * WW + g];
            xs[c * 264 + v * 66 + cc] = val;
        }
    }
    __syncthreads();

    const size_t nbase = (size_t)bz * 16384 + (size_t)ho * 512 + wo0;
    const int wm = (wid & 1) * 32;
    const int wn = (wid >> 1) * 64;

    for (int s = 0; s < 2; s++) {
        // ---- h compute, shfl-paired bf16x2 split: one st.shared.u32 per j ----
        {
            int posl = wid;
            int pos  = 8 * s + posl;
            int u = pos >> 2, v = pos & 3;
            int px = lane;
            float R   = rs[v * 66 + 2 * px + u];
            float nrc = -rs[2 * 66 + 2 * px + 2];
            const uint32_t plane = (lane & 1) ? (sb + HSL_B) : (sb + HSH_B);
            const int wordb = (tid & ~1) * 2;     // byte offset of pair word in row
            #pragma unroll 8
            for (int j = 0; j < 64; j++) {
                float t = fmaf(R, Ast[j * 16 + pos], fmaf(nrc, W10s[j], b1s[j]));
                t = (t > 0.0f) ? t : 0.2f * t;
                __nv_bfloat16 hb = __float2bfloat16(t);
                float rem = t - __bfloat162float(hb);
                float t_o   = __shfl_xor_sync(0xffffffffu, t, 1);
                float rem_o = __shfl_xor_sync(0xffffffffu, rem, 1);
                uint32_t wH = pk_bf2(t, t_o);        // even lane: (even, odd) combos
                uint32_t wL = pk_bf2(rem_o, rem);    // odd lane:  (even, odd) combos
                uint32_t word = (lane & 1) ? wL : wH;
                sts32(plane + SWC(j * 512 + wordb), word);
            }
        }
        __syncthreads();

        // ---- HMMA GEMM: w[c][combo] = b2[c] + sum_j W2T[c][j]*h[j][combo] ----
        {
            float acc[2][8][4];
            #pragma unroll
            for (int mi = 0; mi < 2; mi++)
                #pragma unroll
                for (int nt = 0; nt < 8; nt++)
                    #pragma unroll
                    for (int q = 0; q < 4; q++) acc[mi][nt][q] = 0.0f;

            #pragma unroll
            for (int ks = 0; ks < 4; ks++) {
                uint32_t aH[2][4], aL[2][4];
                int arow  = wm + (lane & 15);
                int acolb = ks * 32 + ((lane >> 4) << 4);
                #pragma unroll
                for (int mi = 0; mi < 2; mi++) {
                    uint32_t off = SWA((arow + mi * 16) * 128 + acolb);
                    ldsm4(aH[mi], sb + W2TH_B + off);
                    ldsm4(aL[mi], sb + W2TL_B + off);
                }
                int browb = (ks * 16 + (lane & 15)) * 512;
                #pragma unroll
                for (int g = 0; g < 4; g++) {
                    uint32_t off = SWC(browb + wn * 2 + g * 32 + ((lane >> 4) << 4));
                    uint32_t bh[4], bl[4];
                    ldsm4t(bh, sb + HSH_B + off);
                    ldsm4t(bl, sb + HSL_B + off);
                    #pragma unroll
                    for (int mi = 0; mi < 2; mi++) {
                        mma16816(acc[mi][2*g],   aH[mi], bh);
                        mma16816(acc[mi][2*g+1], aH[mi], bh + 2);
                        mma16816(acc[mi][2*g],   aL[mi], bh);
                        mma16816(acc[mi][2*g+1], aL[mi], bh + 2);
                        mma16816(acc[mi][2*g],   aH[mi], bl);
                        mma16816(acc[mi][2*g+1], aH[mi], bl + 2);
                    }
                }
            }

            #pragma unroll
            for (int mi = 0; mi < 2; mi++) {
                int r0 = wm + mi * 16 + (lane >> 2);
                float b2a = b2s[r0], b2b = b2s[r0 + 8];
                #pragma unroll
                for (int nt = 0; nt < 8; nt++) {
                    int col = wn + nt * 8 + (lane & 3) * 2;
                    float2 v0, v1;
                    v0.x = acc[mi][nt][0] + b2a; v0.y = acc[mi][nt][1] + b2a;
                    v1.x = acc[mi][nt][2] + b2b; v1.y = acc[mi][nt][3] + b2b;
                    *(float2*)(ws + r0 * 260 + col) = v0;
                    *(float2*)(ws + (r0 + 8) * 260 + col) = v1;
                }
            }
        }
        __syncthreads();

        // ---- phase B: m = w * x (all smem) -> g_m bf16 hi/lo ----
        {
            int posl = wid;
            int pos  = 8 * s + posl;
            int u = pos >> 2, v = pos & 3;
            int px = lane;
            const float* xrow = xs + v * 66 + 2 * px + u;
            const float* wsr  = ws + posl * 32 + px;
            __nv_bfloat16* gmh = g_mh + (size_t)pos * NPIX + nbase + px;
            __nv_bfloat16* gml = g_ml + (size_t)pos * NPIX + nbase + px;
            #pragma unroll 8
            for (int c = 0; c < 64; c++) {
                float wv = wsr[c * 260];
                float xv = xrow[c * 264];
                float mv = wv * xv;
                __nv_bfloat16 hi = __float2bfloat16(mv);
                float rem = mv - __bfloat162float(hi);
                gmh[(size_t)c * 16 * NPIX] = hi;
                gml[(size_t)c * 16 * NPIX] = __float2bfloat16(rem);
            }
        }
        __syncthreads();
    }

    if (rcout != nullptr && tid < 32) {
        rcout[nbase + tid] = rs[2 * 66 + 2 * tid + 2];
    }
}

// =====================================================================
// Kernel 2: HMMA bf16 split GEMM (unchanged, known-good).
// =====================================================================
#define K2_STAGE 65536
#define K2_SMEM  (2 * K2_STAGE)

__global__ void __launch_bounds__(256, 1)
k2_hmma(const float* __restrict__ bc, float* __restrict__ out)
{
    extern __shared__ char sm2[];
    const uint32_t sb = smem_u32(sm2);
    const int tid  = threadIdx.x;
    const int wid  = tid >> 5;
    const int lane = tid & 31;
    const int n0 = blockIdx.x * 128;
    const int wm = (wid & 3) * 32;
    const int wn = (wid >> 2) * 64;

    float acc[2][8][4];
    #pragma unroll
    for (int mi = 0; mi < 2; mi++)
        #pragma unroll
        for (int nt = 0; nt < 8; nt++)
            #pragma unroll
            for (int q = 0; q < 4; q++) acc[mi][nt][q] = 0.0f;

    auto load_chunk = [&](int c, int s) {
        const uint32_t base = sb + s * K2_STAGE;
        const int k0 = c * 64;
        #pragma unroll
        for (int t = 0; t < 16; t++) {
            int ci  = tid + t * 256;
            int sec = t >> 2;
            int ci0 = ci & 1023;
            if (sec < 2) {
                const __nv_bfloat16* W = sec ? g_WcL : g_WcH;
                int row = ci0 >> 3, u = ci0 & 7;
                uint32_t sa = base + sec * 16384 + SWA(row * 128 + u * 16);
                cp16(sa, W + (size_t)row * KTOT + k0 + u * 8);
            } else {
                const __nv_bfloat16* M = (sec == 2) ? g_mh : g_ml;
                int row = ci0 >> 4, u = ci0 & 15;
                uint32_t sa = base + sec * 16384 + SWB(row * 256 + u * 16);
                cp16(sa, M + (size_t)(k0 + row) * NPIX + n0 + u * 8);
            }
        }
        CP_COMMIT();
    };

    load_chunk(0, 0);
    load_chunk(1, 1);

    for (int c = 0; c < 16; c++) {
        const int s = c & 1;
        if (c == 15) { CP_WAIT0(); } else { CP_WAIT1(); }
        __syncthreads();

        const uint32_t bAh = sb + s * K2_STAGE;
        const uint32_t bAl = bAh + 16384;
        const uint32_t bBh = bAh + 32768;
        const uint32_t bBl = bAh + 49152;

        #pragma unroll
        for (int ks = 0; ks < 4; ks++) {
            uint32_t a_h[2][4], a_l[2][4];
            {
                int arow  = wm + (lane & 15);
                int acolb = ks * 32 + ((lane >> 4) << 4);
                #pragma unroll
                for (int mi = 0; mi < 2; mi++) {
                    uint32_t off = SWA((arow + mi * 16) * 128 + acolb);
                    ldsm4(a_h[mi], bAh + off);
                    ldsm4(a_l[mi], bAl + off);
                }
            }
            int brow = ks * 16 + (lane & 15);
            #pragma unroll
            for (int g = 0; g < 4; g++) {
                int bcolb = (wn + g * 16 + ((lane >> 4) << 3)) * 2;
                uint32_t off = SWB(brow * 256 + bcolb);
                uint32_t bh[4], bl[4];
                ldsm4t(bh, bBh + off);
                ldsm4t(bl, bBl + off);
                #pragma unroll
                for (int mi = 0; mi < 2; mi++) {
                    mma16816(acc[mi][2*g],   a_h[mi], bh);
                    mma16816(acc[mi][2*g+1], a_h[mi], bh + 2);
                    mma16816(acc[mi][2*g],   a_l[mi], bh);
                    mma16816(acc[mi][2*g+1], a_l[mi], bh + 2);
                    mma16816(acc[mi][2*g],   a_h[mi], bl);
                    mma16816(acc[mi][2*g+1], a_h[mi], bl + 2);
                }
            }
        }
        __syncthreads();
        if (c + 2 < 16) load_chunk(c + 2, s);
    }

    const int bz = n0 >> 14;
    #pragma unroll
    for (int mi = 0; mi < 2; mi++) {
        int r0 = wm + mi * 16 + (lane >> 2);
        float bv0 = bc[r0], bv1 = bc[r0 + 8];
        float* row0 = out + ((size_t)(bz * COUT + r0))     * 16384 + (n0 & 16383);
        float* row1 = out + ((size_t)(bz * COUT + r0 + 8)) * 16384 + (n0 & 16383);
        #pragma unroll
        for (int nt = 0; nt < 8; nt++) {
            int col = wn + nt * 8 + (lane & 3) * 2;
            float2 v0, v1;
            v0.x = acc[mi][nt][0] + bv0; v0.y = acc[mi][nt][1] + bv0;
            v1.x = acc[mi][nt][2] + bv1; v1.y = acc[mi][nt][3] + bv1;
            *(float2*)(row0 + col) = v0;
            *(float2*)(row1 + col) = v1;
        }
    }
}

extern "C" void kernel_launch(void* const* d_in, const int* in_sizes, int n_in,
                              void* d_out, int out_size) {
    const float* x  = (const float*)d_in[0];
    const float* r  = (const float*)d_in[1];
    const float* W1 = (const float*)d_in[2];
    const float* b1 = (const float*)d_in[3];
    const float* W2 = (const float*)d_in[4];
    const float* b2 = (const float*)d_in[5];
    const float* Wc = (const float*)d_in[6];
    const float* bc = (const float*)d_in[7];
    float* out = (float*)d_out;

    cudaFuncSetAttribute(k1_weights, cudaFuncAttributeMaxDynamicSharedMemorySize, SM1_BYTES);
    cudaFuncSetAttribute(k2_hmma, cudaFuncAttributeMaxDynamicSharedMemorySize, K2_SMEM);

    float* rcout = (out_size > OUT0) ? (out + OUT0) : nullptr;

    k0_prep<<<(COUT * KTOT + 255) / 256, 256>>>(Wc, W2, W1);
    dim3 g1(16, 32, 4);
    k1_weights<<<g1, 256, SM1_BYTES>>>(x, r, W1, b1, b2, rcout);
    k2_hmma<<<512, 256, K2_SMEM>>>(bc, out);
}